// round 15
// baseline (speedup 1.0000x reference)
#include <cuda_runtime.h>
#include <cstdint>

#define Hh 128
#define Ww 128
#define HW (128*128)
#define Bb 8
#define Gg 2
#define GC 32
#define SC 288
#define GF 64

// ---------------- scratch (allocation-free: __device__ global) ----------------
__device__ float g_off[(size_t)Bb*Gg*HW*18];          // offsets, [bg][p][k][2]

// ---------------- f32x2 packed helpers ----------------
__device__ __forceinline__ unsigned long long pack2(float a, float b) {
    unsigned long long d;
    asm("mov.b64 %0, {%1, %2};" : "=l"(d) : "f"(a), "f"(b));
    return d;
}
__device__ __forceinline__ float2 unpack2(unsigned long long v) {
    float2 r;
    asm("mov.b64 {%0, %1}, %2;" : "=f"(r.x), "=f"(r.y) : "l"(v));
    return r;
}
__device__ __forceinline__ unsigned long long fma2(unsigned long long a,
                                                   unsigned long long b,
                                                   unsigned long long c) {
    unsigned long long d;
    asm("fma.rn.f32x2 %0, %1, %2, %3;" : "=l"(d) : "l"(a), "l"(b), "l"(c));
    return d;
}

// =====================================================================
// Kernel A: offset conv (3x3, 32 -> 18 ch, SAME, per group)  [unchanged]
// =====================================================================
__global__ void __launch_bounds__(256, 3) k_offconv(const float* __restrict__ x,
                                                    const float* __restrict__ ow,
                                                    const float* __restrict__ ob)
{
    extern __shared__ float s[];
    float* s_in = s;                         // 18*18*33 = 10692 (scalar access only)
    float* s_w  = s + 10692;                 // 9*32*18  = 5184

    const int bg = blockIdx.z;
    const int b = bg >> 1, g = bg & 1;
    const int tx0 = blockIdx.x * 16, ty0 = blockIdx.y * 16;
    const float* xb = x + (size_t)b * HW * 64 + g * 32;
    const float* wg = ow + (size_t)g * 9 * 32 * 18;

    for (int i = threadIdx.x; i < 9 * 32 * 18; i += 256) s_w[i] = wg[i];

    for (int i = threadIdx.x; i < 324 * 32; i += 256) {
        int c   = i & 31;
        int pos = i >> 5;
        int col = pos % 18, row = pos / 18;
        int gy = ty0 - 1 + row, gx = tx0 - 1 + col;
        float v = 0.f;
        if ((unsigned)gy < Hh && (unsigned)gx < Ww)
            v = xb[(size_t)(gy * Ww + gx) * 64 + c];
        s_in[pos * 33 + c] = v;
    }
    __syncthreads();

    const int tx = threadIdx.x & 15, ty = threadIdx.x >> 4;

    unsigned long long acc[9];
    const float2* ob2 = (const float2*)(ob + g * 18);
#pragma unroll
    for (int j = 0; j < 9; j++) {
        float2 bb = ob2[j];
        acc[j] = pack2(bb.x, bb.y);
    }

#pragma unroll
    for (int ky = 0; ky < 3; ky++) {
#pragma unroll
        for (int kx = 0; kx < 3; kx++) {
            const float* wt = s_w + (size_t)((ky * 3 + kx) * 32) * 18;
            const int sb0 = ((ty + ky) * 18 + tx + kx) * 33;
#pragma unroll 8
            for (int c = 0; c < 32; c++) {
                float v0 = s_in[sb0 + c];
                unsigned long long p0 = pack2(v0, v0);
                const unsigned long long* wp =
                    (const unsigned long long*)(wt + c * 18);
#pragma unroll
                for (int j = 0; j < 9; j++)
                    acc[j] = fma2(p0, wp[j], acc[j]);
            }
        }
    }

    unsigned long long* o0 = (unsigned long long*)(g_off +
        ((size_t)bg * HW + (ty0 + ty) * Ww + (tx0 + tx)) * 18);
#pragma unroll
    for (int j = 0; j < 9; j++) o0[j] = acc[j];
}

// =====================================================================
// Kernel C (fused): bilinear sampling + depthwise 3x3 + pointwise (SC->64).
// R14 restructure (issue-bound at occ 23%, so cut instructions):
//  - stage A: thread = halo pos; clip math ONCE per pos (was 8x); 32
//    independent LDG.128 gathers per pos (deep MLP).
//  - phase 1: thread = (ch, 16px row); halo cols reused across row
//    (126 vs 216 LDS/thread/tap); dwb staged in smem.
//  - phase 2: pw weights pre-duplicated (w,w) u64 in smem -> no pack2.
// =====================================================================
__global__ void __launch_bounds__(256, 2) k_fused(const float* __restrict__ x,
                                                  const float* __restrict__ dww,
                                                  const float* __restrict__ dwb,
                                                  const float* __restrict__ pww,
                                                  const float* __restrict__ pwb,
                                                  float* __restrict__ out)
{
    extern __shared__ float sm[];
    float* sA  = sm;                          // 324*36  = 11664 (halo samples)
    float* dsh = sm + 11664;                  // 32*260  = 8320  (dw out, [ch][pix])
    float* sW  = sm + 11664 + 8320;           // 9*288   = 2592  (dw weights)
    float* sB  = sm + 11664 + 8320 + 2592;    // 288           (dw bias)
    unsigned long long* sP2 =                 // 32*64 u64 = 4096 floats
        (unsigned long long*)(sm + 11664 + 8320 + 2592 + 288);
    // total 26960 floats = 107840 B; x2 blocks = 215.7KB < 228KB

    const int bg = blockIdx.z;
    const int b = bg >> 1, g = bg & 1;
    const int tx0 = blockIdx.x * 16, ty0 = blockIdx.y * 16;
    const int tid = threadIdx.x;
    const int lane = tid & 31, fg = tid >> 5;
    const float* xg = x + (size_t)b * HW * 64 + g * 32;
    const float2* offb = (const float2*)g_off + (size_t)bg * HW * 9;

    // stage depthwise weights + bias once
    for (int i = tid; i < 9 * SC; i += 256) sW[i] = dww[(size_t)g * 9 * SC + i];
    for (int i = tid; i < SC; i += 256)     sB[i] = dwb[g * SC + i];

    unsigned long long acc[8][4];
#pragma unroll
    for (int f = 0; f < 8; f++)
#pragma unroll
        for (int q = 0; q < 4; q++) acc[f][q] = 0ull;

    const float dxk[3] = {-1.f, 0.f, 1.f};

    for (int k = 0; k < 9; k++) {
        const int c0 = k * 32;
        const float dx = dxk[k % 3], dy = dxk[k / 3];
        __syncthreads();   // prev phase-2 done reading dsh/sP2 before restage

        // ----- stage A: sample halo tile; thread = one halo pos (all 32ch) -----
        for (int p = tid; p < 324; p += 256) {
            const int col = p % 18, row = p / 18;
            const int gy = ty0 - 1 + row, gx = tx0 - 1 + col;
            float* dst = &sA[p * 36];
            if ((unsigned)gy < Hh && (unsigned)gx < Ww) {
                const float2 off2 = offb[(size_t)(gy * Ww + gx) * 9 + k];
                float lx = (float)gx + dx + off2.x;
                float ly = (float)gy + dy + off2.y;
                lx = fminf(fmaxf(lx, 0.f), 127.f);
                ly = fminf(fmaxf(ly, 0.f), 127.f);
                float fx = floorf(lx), fy = floorf(ly);
                float x0f = fminf(fmaxf(fx, 0.f), 127.f);
                float x1f = fminf(fmaxf(fx + 1.f, 0.f), 127.f);
                float y0f = fminf(fmaxf(fy, 0.f), 127.f);
                float y1f = fminf(fmaxf(fy + 1.f, 0.f), 127.f);
                float wa = (x1f - lx) * (y1f - ly);
                float wb = (x1f - lx) * (ly - y0f);
                float wc = (lx - x0f) * (y1f - ly);
                float wd = (lx - x0f) * (ly - y0f);
                int x0 = (int)x0f, x1 = (int)x1f, y0 = (int)y0f, y1 = (int)y1f;
                const float* pa = xg + (size_t)(y0 * Ww + x0) * 64;
                const float* pb = xg + (size_t)(y1 * Ww + x0) * 64;
                const float* pc = xg + (size_t)(y0 * Ww + x1) * 64;
                const float* pd = xg + (size_t)(y1 * Ww + x1) * 64;
#pragma unroll
                for (int c4 = 0; c4 < 8; c4++) {
                    const float4 Ia = *(const float4*)(pa + c4 * 4);
                    const float4 Ib = *(const float4*)(pb + c4 * 4);
                    const float4 Ic = *(const float4*)(pc + c4 * 4);
                    const float4 Id = *(const float4*)(pd + c4 * 4);
                    float4 r;
                    r.x = wa * Ia.x + wb * Ib.x + wc * Ic.x + wd * Id.x;
                    r.y = wa * Ia.y + wb * Ib.y + wc * Ic.y + wd * Id.y;
                    r.z = wa * Ia.z + wb * Ib.z + wc * Ic.z + wd * Id.z;
                    r.w = wa * Ia.w + wb * Ib.w + wc * Ic.w + wd * Id.w;
                    *(float4*)(dst + c4 * 4) = r;
                }
            } else {
#pragma unroll
                for (int c4 = 0; c4 < 8; c4++)
                    *(float4*)(dst + c4 * 4) = make_float4(0.f, 0.f, 0.f, 0.f);
            }
        }
        // ----- stage B: pw weight slab, pre-duplicated (w,w) pairs -----
        for (int i = tid; i < 32 * 64; i += 256) {
            const float w = pww[((size_t)g * SC + c0) * 64 + i];
            sP2[i] = pack2(w, w);
        }
        __syncthreads();

        // ----- phase 1: depthwise; thread = (ch, 16-pixel row) -----
        for (int u = tid; u < 512; u += 256) {
            const int ch = u & 31;           // lanes: consecutive ch
            const int py = u >> 5;
            float a[16];
            const float bs = sB[c0 + ch];
#pragma unroll
            for (int px = 0; px < 16; px++) a[px] = bs;
#pragma unroll
            for (int ky = 0; ky < 3; ky++) {
                const float w0 = sW[(ky * 3 + 0) * SC + c0 + ch];
                const float w1 = sW[(ky * 3 + 1) * SC + c0 + ch];
                const float w2 = sW[(ky * 3 + 2) * SC + c0 + ch];
                const int rb = (py + ky) * 18 * 36 + ch;
                float c[18];
#pragma unroll
                for (int j = 0; j < 18; j++) c[j] = sA[rb + j * 36];
#pragma unroll
                for (int px = 0; px < 16; px++)
                    a[px] += w0 * c[px] + w1 * c[px + 1] + w2 * c[px + 2];
            }
            float* dst = &dsh[ch * 260 + py * 16];
#pragma unroll
            for (int q = 0; q < 4; q++)
                *(float4*)(dst + q * 4) =
                    make_float4(a[q*4], a[q*4+1], a[q*4+2], a[q*4+3]);
        }
        __syncthreads();

        // ----- phase 2: pointwise GEMM over this 32-channel chunk -----
#pragma unroll 4
        for (int chl = 0; chl < 32; chl++) {
            const ulonglong2* dp = (const ulonglong2*)&dsh[chl * 260 + lane * 8];
            const ulonglong2 dA = dp[0];
            const ulonglong2 dB = dp[1];
            const ulonglong2* wv = (const ulonglong2*)(sP2 + chl * 64 + fg * 8);
            const ulonglong2 wA = wv[0];   // (f0,f0),(f1,f1)
            const ulonglong2 wB = wv[1];   // (f2,f2),(f3,f3)
            const ulonglong2 wC = wv[2];
            const ulonglong2 wD = wv[3];
            const unsigned long long wp[8] = {wA.x, wA.y, wB.x, wB.y,
                                              wC.x, wC.y, wD.x, wD.y};
#pragma unroll
            for (int f = 0; f < 8; f++) {
                acc[f][0] = fma2(dA.x, wp[f], acc[f][0]);
                acc[f][1] = fma2(dA.y, wp[f], acc[f][1]);
                acc[f][2] = fma2(dB.x, wp[f], acc[f][2]);
                acc[f][3] = fma2(dB.y, wp[f], acc[f][3]);
            }
        }
    }

    // ----- epilogue: bias + store -----
    float bias[8];
#pragma unroll
    for (int f = 0; f < 8; f++) bias[f] = pwb[g * 64 + fg * 8 + f];

#pragma unroll
    for (int pp = 0; pp < 4; pp++) {
        float2 u[8];
#pragma unroll
        for (int f = 0; f < 8; f++) u[f] = unpack2(acc[f][pp]);
#pragma unroll
        for (int half = 0; half < 2; half++) {
            const int lpix = lane * 8 + pp * 2 + half;
            const int py = lpix >> 4, px = lpix & 15;
            float* op = out + ((size_t)b * HW + (ty0 + py) * Ww + (tx0 + px)) * 128
                        + g * 64 + fg * 8;
            float v[8];
#pragma unroll
            for (int f = 0; f < 8; f++)
                v[f] = (half ? u[f].y : u[f].x) + bias[f];
            ((float4*)op)[0] = make_float4(v[0], v[1], v[2], v[3]);
            ((float4*)op)[1] = make_float4(v[4], v[5], v[6], v[7]);
        }
    }
}

// =====================================================================
// launch
// =====================================================================
extern "C" void kernel_launch(void* const* d_in, const int* in_sizes, int n_in,
                              void* d_out, int out_size)
{
    const float* x    = (const float*)d_in[0];
    const float* ow   = (const float*)d_in[1];
    const float* obia = (const float*)d_in[2];
    const float* dww  = (const float*)d_in[3];
    const float* dwbi = (const float*)d_in[4];
    const float* pww  = (const float*)d_in[5];
    const float* pwbi = (const float*)d_in[6];
    float* out = (float*)d_out;

    const int smemA = (10692 + 5184) * 4;                        // 63504 B
    const int smemC = (11664 + 8320 + 2592 + 288 + 4096) * 4;    // 107840 B
    cudaFuncSetAttribute(k_offconv, cudaFuncAttributeMaxDynamicSharedMemorySize, smemA);
    cudaFuncSetAttribute(k_fused,   cudaFuncAttributeMaxDynamicSharedMemorySize, smemC);

    k_offconv<<<dim3(8, 8, Bb * Gg), 256, smemA>>>(x, ow, obia);
    k_fused<<<dim3(8, 8, Bb * Gg), 256, smemC>>>(x, dww, dwbi, pww, pwbi, out);
}